// round 10
// baseline (speedup 1.0000x reference)
#include <cuda_runtime.h>
#include <cuda_fp16.h>
#include <cstdint>

#define MAXN 50000
#define MAXE 1600000
#define F_IN 128
#define HID  128
#define F_OUT 64

// ---- scratch (device globals; no allocation allowed) ----
__device__ int    g_cnt[MAXN];
__device__ int    g_rowtmp[MAXN];
__device__ int    g_bsum[256];
__device__ int    g_rowptr[MAXN + 1];
__device__ int    g_wp[MAXN];
__device__ float  g_dinv[MAXN];
__device__ int2   g_edge[MAXE];                 // .x = src, .y = bits(norm)
__device__ __half g_h1h[(size_t)MAXN * HID];    // fp16 x@W1 (gather operand)
__device__ float  g_agg1[(size_t)MAXN * HID];   // fp32 aggregated layer-1
__device__ __half g_h2h[(size_t)MAXN * F_OUT];  // fp16 layer-2 pre-agg

// ---------------------------------------------------------------------------
__global__ void k_hist(const int* __restrict__ ei, int e) {
    int i = blockIdx.x * blockDim.x + threadIdx.x;
    if (i < e) atomicAdd(&g_cnt[ei[e + i]], 1);
}

// block-local inclusive scan of g_cnt; block totals to g_bsum
__global__ void k_scan_a(int n) {
    __shared__ int s[256];
    int i = blockIdx.x * 256 + threadIdx.x;
    int v = (i < n) ? g_cnt[i] : 0;
    s[threadIdx.x] = v;
    __syncthreads();
#pragma unroll
    for (int off = 1; off < 256; off <<= 1) {
        int t = (threadIdx.x >= off) ? s[threadIdx.x - off] : 0;
        __syncthreads();
        s[threadIdx.x] += t;
        __syncthreads();
    }
    if (i < n) g_rowtmp[i] = s[threadIdx.x];
    if (threadIdx.x == 255) g_bsum[blockIdx.x] = s[255];
}

// fused: per-block reduce of prior block sums + rowptr + wp + dinv
__global__ void k_scan_c(int n, int e) {
    __shared__ int red[8];
    __shared__ int s_off;
    int partial = 0;
    for (int j = threadIdx.x; j < blockIdx.x; j += 256) partial += g_bsum[j];
#pragma unroll
    for (int o = 16; o; o >>= 1) partial += __shfl_down_sync(0xffffffffu, partial, o);
    if ((threadIdx.x & 31) == 0) red[threadIdx.x >> 5] = partial;
    __syncthreads();
    if (threadIdx.x == 0) {
        int t = 0;
#pragma unroll
        for (int k = 0; k < 8; k++) t += red[k];
        s_off = t;
    }
    __syncthreads();
    int i = blockIdx.x * 256 + threadIdx.x;
    if (i < n) {
        int c = g_cnt[i];
        int rp = s_off + g_rowtmp[i] - c;  // exclusive prefix
        g_rowptr[i] = rp;
        g_wp[i] = rp;
        g_dinv[i] = rsqrtf((float)c + 1.0f);
    }
    if (i == 0) g_rowptr[n] = e;
}

__global__ void k_scatter(const int* __restrict__ ei, int e) {
    int i = blockIdx.x * blockDim.x + threadIdx.x;
    if (i >= e) return;
    int src = ei[i], dst = ei[e + i];
    int pos = atomicAdd(&g_wp[dst], 1);
    float nrm = g_dinv[src] * g_dinv[dst];
    g_edge[pos] = make_int2(src, __float_as_int(nrm));
}

// ---------------------------------------------------------------------------
// GEMM1: h1[n,128] = x[n,128] @ W1[128,128], stored fp16
__global__ void k_gemm1(const float* __restrict__ x, const float* __restrict__ W1, int n) {
    __shared__ float xs[64 * F_IN];
    int base = blockIdx.x * 64;
    const float4* xv = (const float4*)x;
    float4* xsv = (float4*)xs;
    for (int i = threadIdx.x; i < 64 * 32; i += 256) {
        int node = i >> 5, c = i & 31;
        xsv[i] = (base + node < n) ? xv[(size_t)(base + node) * 32 + c]
                                   : make_float4(0.f, 0.f, 0.f, 0.f);
    }
    __syncthreads();
    int j4 = threadIdx.x & 31;   // 4 features
    int ng = threadIdx.x >> 5;   // 8 nodes
    const float4* Wv = (const float4*)W1;
    float acc[8][4];
#pragma unroll
    for (int t = 0; t < 8; t++) { acc[t][0]=acc[t][1]=acc[t][2]=acc[t][3]=0.f; }
#pragma unroll 4
    for (int k = 0; k < F_IN; k++) {
        float4 wk = Wv[k * 32 + j4];
#pragma unroll
        for (int t = 0; t < 8; t++) {
            float xx = xs[(ng * 8 + t) * F_IN + k];
            acc[t][0] += xx * wk.x;
            acc[t][1] += xx * wk.y;
            acc[t][2] += xx * wk.z;
            acc[t][3] += xx * wk.w;
        }
    }
    uint2* h1v = (uint2*)g_h1h;
#pragma unroll
    for (int t = 0; t < 8; t++) {
        int node = base + ng * 8 + t;
        if (node < n) {
            __half2 lo = __floats2half2_rn(acc[t][0], acc[t][1]);
            __half2 hi = __floats2half2_rn(acc[t][2], acc[t][3]);
            h1v[(size_t)node * 32 + j4] =
                make_uint2(*(unsigned*)&lo, *(unsigned*)&hi);
        }
    }
}

// ---------------------------------------------------------------------------
// Layer-1 pull aggregation: warp per node, 4 fp16 feats/lane, fp32 acc.
__global__ void k_agg1(int n) {
    int w = (blockIdx.x * blockDim.x + threadIdx.x) >> 5;
    int lane = threadIdx.x & 31;
    if (w >= n) return;
    int beg = g_rowptr[w], end = g_rowptr[w + 1];
    float di = g_dinv[w];
    const uint2* hb = (const uint2*)g_h1h;

    uint2 sv = hb[(size_t)w * 32 + lane];
    float2 s0 = __half22float2(*(__half2*)&sv.x);
    float2 s1 = __half22float2(*(__half2*)&sv.y);
    float s = di * di;
    float4 acc = make_float4(s0.x * s, s0.y * s, s1.x * s, s1.y * s);

    int p = beg;
    for (; p + 4 <= end; p += 4) {
        int2 e0 = g_edge[p], e1 = g_edge[p + 1], e2 = g_edge[p + 2], e3 = g_edge[p + 3];
        uint2 u0 = hb[(size_t)e0.x * 32 + lane];
        uint2 u1 = hb[(size_t)e1.x * 32 + lane];
        uint2 u2 = hb[(size_t)e2.x * 32 + lane];
        uint2 u3 = hb[(size_t)e3.x * 32 + lane];
        float w0 = __int_as_float(e0.y), w1 = __int_as_float(e1.y);
        float w2 = __int_as_float(e2.y), w3 = __int_as_float(e3.y);
        float2 a, b;
        a = __half22float2(*(__half2*)&u0.x); b = __half22float2(*(__half2*)&u0.y);
        acc.x += w0 * a.x; acc.y += w0 * a.y; acc.z += w0 * b.x; acc.w += w0 * b.y;
        a = __half22float2(*(__half2*)&u1.x); b = __half22float2(*(__half2*)&u1.y);
        acc.x += w1 * a.x; acc.y += w1 * a.y; acc.z += w1 * b.x; acc.w += w1 * b.y;
        a = __half22float2(*(__half2*)&u2.x); b = __half22float2(*(__half2*)&u2.y);
        acc.x += w2 * a.x; acc.y += w2 * a.y; acc.z += w2 * b.x; acc.w += w2 * b.y;
        a = __half22float2(*(__half2*)&u3.x); b = __half22float2(*(__half2*)&u3.y);
        acc.x += w3 * a.x; acc.y += w3 * a.y; acc.z += w3 * b.x; acc.w += w3 * b.y;
    }
    for (; p < end; p++) {
        int2 e0 = g_edge[p];
        uint2 u0 = hb[(size_t)e0.x * 32 + lane];
        float w0 = __int_as_float(e0.y);
        float2 a = __half22float2(*(__half2*)&u0.x);
        float2 b = __half22float2(*(__half2*)&u0.y);
        acc.x += w0 * a.x; acc.y += w0 * a.y; acc.z += w0 * b.x; acc.w += w0 * b.y;
    }
    ((float4*)g_agg1)[(size_t)w * 32 + lane] = acc;
}

// ---------------------------------------------------------------------------
// GEMM2: h2[n,64] = relu(agg1 + b1) @ W2[128,64], stored fp16
__global__ void k_gemm2(const float* __restrict__ b1, const float* __restrict__ W2, int n) {
    __shared__ float xs[64 * HID];
    __shared__ float bs[HID];
    int base = blockIdx.x * 64;
    if (threadIdx.x < HID) bs[threadIdx.x] = b1[threadIdx.x];
    __syncthreads();
    for (int i = threadIdx.x; i < 64 * HID; i += 256) {
        int node = i >> 7, k = i & 127;
        float v = (base + node < n) ? g_agg1[(size_t)(base + node) * HID + k] + bs[k] : 0.f;
        xs[i] = fmaxf(v, 0.f);
    }
    __syncthreads();
    int j4 = threadIdx.x & 15;   // 4 features
    int ng = threadIdx.x >> 4;   // 4 nodes
    const float4* Wv = (const float4*)W2;
    float acc[4][4];
#pragma unroll
    for (int t = 0; t < 4; t++) { acc[t][0]=acc[t][1]=acc[t][2]=acc[t][3]=0.f; }
#pragma unroll 4
    for (int k = 0; k < HID; k++) {
        float4 wk = Wv[k * 16 + j4];
#pragma unroll
        for (int t = 0; t < 4; t++) {
            float xx = xs[(ng * 4 + t) * HID + k];
            acc[t][0] += xx * wk.x;
            acc[t][1] += xx * wk.y;
            acc[t][2] += xx * wk.z;
            acc[t][3] += xx * wk.w;
        }
    }
    uint2* h2v = (uint2*)g_h2h;
#pragma unroll
    for (int t = 0; t < 4; t++) {
        int node = base + ng * 4 + t;
        if (node < n) {
            __half2 lo = __floats2half2_rn(acc[t][0], acc[t][1]);
            __half2 hi = __floats2half2_rn(acc[t][2], acc[t][3]);
            h2v[(size_t)node * 16 + j4] =
                make_uint2(*(unsigned*)&lo, *(unsigned*)&hi);
        }
    }
}

// ---------------------------------------------------------------------------
// Layer-2 pull aggregation + bias + ReLU: warp per node, 2 fp16 feats/lane.
__global__ void k_agg2(float* __restrict__ out, const float* __restrict__ b2, int n) {
    int w = (blockIdx.x * blockDim.x + threadIdx.x) >> 5;
    int lane = threadIdx.x & 31;
    if (w >= n) return;
    int beg = g_rowptr[w], end = g_rowptr[w + 1];
    float di = g_dinv[w];
    const unsigned* hb = (const unsigned*)g_h2h;

    unsigned sv = hb[(size_t)w * 32 + lane];
    float2 s0 = __half22float2(*(__half2*)&sv);
    float s = di * di;
    float2 acc = make_float2(s0.x * s, s0.y * s);

    int p = beg;
    for (; p + 4 <= end; p += 4) {
        int2 e0 = g_edge[p], e1 = g_edge[p + 1], e2 = g_edge[p + 2], e3 = g_edge[p + 3];
        unsigned u0 = hb[(size_t)e0.x * 32 + lane];
        unsigned u1 = hb[(size_t)e1.x * 32 + lane];
        unsigned u2 = hb[(size_t)e2.x * 32 + lane];
        unsigned u3 = hb[(size_t)e3.x * 32 + lane];
        float w0 = __int_as_float(e0.y), w1 = __int_as_float(e1.y);
        float w2 = __int_as_float(e2.y), w3 = __int_as_float(e3.y);
        float2 a;
        a = __half22float2(*(__half2*)&u0); acc.x += w0 * a.x; acc.y += w0 * a.y;
        a = __half22float2(*(__half2*)&u1); acc.x += w1 * a.x; acc.y += w1 * a.y;
        a = __half22float2(*(__half2*)&u2); acc.x += w2 * a.x; acc.y += w2 * a.y;
        a = __half22float2(*(__half2*)&u3); acc.x += w3 * a.x; acc.y += w3 * a.y;
    }
    for (; p < end; p++) {
        int2 e0 = g_edge[p];
        unsigned u0 = hb[(size_t)e0.x * 32 + lane];
        float w0 = __int_as_float(e0.y);
        float2 a = __half22float2(*(__half2*)&u0);
        acc.x += w0 * a.x; acc.y += w0 * a.y;
    }
    float bx = b2[lane * 2], by = b2[lane * 2 + 1];
    ((float2*)out)[(size_t)w * 32 + lane] =
        make_float2(fmaxf(acc.x + bx, 0.f), fmaxf(acc.y + by, 0.f));
}

// ---------------------------------------------------------------------------
extern "C" void kernel_launch(void* const* d_in, const int* in_sizes, int n_in,
                              void* d_out, int out_size) {
    const float* x  = (const float*)d_in[0];
    const int*   ei = (const int*)d_in[1];
    const float* W1 = (const float*)d_in[2];
    const float* b1 = (const float*)d_in[3];
    const float* W2 = (const float*)d_in[4];
    const float* b2 = (const float*)d_in[5];
    float* out = (float*)d_out;

    int n = in_sizes[0] / F_IN;
    int e = in_sizes[1] / 2;
    int nb = (n + 255) / 256;

    // one-time infra (created on first call = correctness run, outside capture;
    // identical launch sequence every call)
    static cudaStream_t s2 = nullptr;
    static cudaEvent_t evRoot = nullptr, evJoin = nullptr;
    if (!s2) {
        cudaStreamCreateWithFlags(&s2, cudaStreamNonBlocking);
        cudaEventCreateWithFlags(&evRoot, cudaEventDisableTiming);
        cudaEventCreateWithFlags(&evJoin, cudaEventDisableTiming);
    }

    void* cntPtr = nullptr;
    cudaGetSymbolAddress(&cntPtr, g_cnt);

    // fork: GEMM1 (x,W1 only) runs concurrently with the CSR build
    cudaEventRecord(evRoot, 0);
    cudaStreamWaitEvent(s2, evRoot, 0);
    k_gemm1<<<(n + 63) / 64, 256, 0, s2>>>(x, W1, n);
    cudaEventRecord(evJoin, s2);

    // CSR build chain on capture (default) stream
    cudaMemsetAsync(cntPtr, 0, (size_t)n * sizeof(int), 0);
    k_hist<<<(e + 255) / 256, 256>>>(ei, e);
    k_scan_a<<<nb, 256>>>(n);
    k_scan_c<<<nb, 256>>>(n, e);
    k_scatter<<<(e + 255) / 256, 256>>>(ei, e);

    // join: agg1 needs both h1 (s2) and CSR (default)
    cudaStreamWaitEvent(0, evJoin, 0);
    {
        long long thr = (long long)n * 32;
        k_agg1<<<(int)((thr + 255) / 256), 256>>>(n);
    }
    k_gemm2<<<(n + 63) / 64, 256>>>(b1, W2, n);
    {
        long long thr = (long long)n * 32;
        k_agg2<<<(int)((thr + 255) / 256), 256>>>(out, b2, n);
    }
}

// round 11
// speedup vs baseline: 1.0062x; 1.0062x over previous
#include <cuda_runtime.h>
#include <cuda_fp16.h>
#include <cstdint>

#define MAXN 50000
#define MAXE 1600000
#define F_IN 128
#define HID  128
#define F_OUT 64

// ---- scratch (device globals; no allocation allowed) ----
__device__ int    g_cnt[MAXN];
__device__ int    g_rowtmp[MAXN];
__device__ int    g_bsum[256];
__device__ int    g_rowptr[MAXN + 1];
__device__ int    g_wp[MAXN];
__device__ float  g_dinv[MAXN];
__device__ int2   g_edge[MAXE];                 // .x = src, .y = bits(norm)
__device__ __half g_h1h[(size_t)MAXN * HID];    // fp16 x@W1 (gather operand)
__device__ float  g_agg1[(size_t)MAXN * HID];   // fp32 aggregated layer-1
__device__ __half g_h2h[(size_t)MAXN * F_OUT];  // fp16 layer-2 pre-agg

// ---------------------------------------------------------------------------
__global__ void k_hist(const int* __restrict__ ei, int e) {
    int i = blockIdx.x * blockDim.x + threadIdx.x;
    if (i < e) atomicAdd(&g_cnt[ei[e + i]], 1);
}

// block-local inclusive scan of g_cnt; block totals to g_bsum
__global__ void k_scan_a(int n) {
    __shared__ int s[256];
    int i = blockIdx.x * 256 + threadIdx.x;
    int v = (i < n) ? g_cnt[i] : 0;
    s[threadIdx.x] = v;
    __syncthreads();
#pragma unroll
    for (int off = 1; off < 256; off <<= 1) {
        int t = (threadIdx.x >= off) ? s[threadIdx.x - off] : 0;
        __syncthreads();
        s[threadIdx.x] += t;
        __syncthreads();
    }
    if (i < n) g_rowtmp[i] = s[threadIdx.x];
    if (threadIdx.x == 255) g_bsum[blockIdx.x] = s[255];
}

// fused: per-block reduce of prior block sums + rowptr + wp + dinv
__global__ void k_scan_c(int n, int e) {
    __shared__ int red[8];
    __shared__ int s_off;
    int partial = 0;
    for (int j = threadIdx.x; j < blockIdx.x; j += 256) partial += g_bsum[j];
#pragma unroll
    for (int o = 16; o; o >>= 1) partial += __shfl_down_sync(0xffffffffu, partial, o);
    if ((threadIdx.x & 31) == 0) red[threadIdx.x >> 5] = partial;
    __syncthreads();
    if (threadIdx.x == 0) {
        int t = 0;
#pragma unroll
        for (int k = 0; k < 8; k++) t += red[k];
        s_off = t;
    }
    __syncthreads();
    int i = blockIdx.x * 256 + threadIdx.x;
    if (i < n) {
        int c = g_cnt[i];
        int rp = s_off + g_rowtmp[i] - c;  // exclusive prefix
        g_rowptr[i] = rp;
        g_wp[i] = rp;
        g_dinv[i] = rsqrtf((float)c + 1.0f);
    }
    if (i == 0) g_rowptr[n] = e;
}

__global__ void k_scatter(const int* __restrict__ ei, int e) {
    int i = blockIdx.x * blockDim.x + threadIdx.x;
    if (i >= e) return;
    int src = ei[i], dst = ei[e + i];
    int pos = atomicAdd(&g_wp[dst], 1);
    float nrm = g_dinv[src] * g_dinv[dst];
    g_edge[pos] = make_int2(src, __float_as_int(nrm));
}

// ---------------------------------------------------------------------------
// GEMM1: h1[n,128] = x[n,128] @ W1[128,128], stored fp16
__global__ void k_gemm1(const float* __restrict__ x, const float* __restrict__ W1, int n) {
    __shared__ float xs[64 * F_IN];
    int base = blockIdx.x * 64;
    const float4* xv = (const float4*)x;
    float4* xsv = (float4*)xs;
    for (int i = threadIdx.x; i < 64 * 32; i += 256) {
        int node = i >> 5, c = i & 31;
        xsv[i] = (base + node < n) ? xv[(size_t)(base + node) * 32 + c]
                                   : make_float4(0.f, 0.f, 0.f, 0.f);
    }
    __syncthreads();
    int j4 = threadIdx.x & 31;   // 4 features
    int ng = threadIdx.x >> 5;   // 8 nodes
    const float4* Wv = (const float4*)W1;
    float acc[8][4];
#pragma unroll
    for (int t = 0; t < 8; t++) { acc[t][0]=acc[t][1]=acc[t][2]=acc[t][3]=0.f; }
#pragma unroll 4
    for (int k = 0; k < F_IN; k++) {
        float4 wk = Wv[k * 32 + j4];
#pragma unroll
        for (int t = 0; t < 8; t++) {
            float xx = xs[(ng * 8 + t) * F_IN + k];
            acc[t][0] += xx * wk.x;
            acc[t][1] += xx * wk.y;
            acc[t][2] += xx * wk.z;
            acc[t][3] += xx * wk.w;
        }
    }
    uint2* h1v = (uint2*)g_h1h;
#pragma unroll
    for (int t = 0; t < 8; t++) {
        int node = base + ng * 8 + t;
        if (node < n) {
            __half2 lo = __floats2half2_rn(acc[t][0], acc[t][1]);
            __half2 hi = __floats2half2_rn(acc[t][2], acc[t][3]);
            h1v[(size_t)node * 32 + j4] =
                make_uint2(*(unsigned*)&lo, *(unsigned*)&hi);
        }
    }
}

// ---------------------------------------------------------------------------
// Layer-1 pull aggregation: warp per node, 4 fp16 feats/lane, fp32 acc.
__global__ void k_agg1(int n) {
    int w = (blockIdx.x * blockDim.x + threadIdx.x) >> 5;
    int lane = threadIdx.x & 31;
    if (w >= n) return;
    int beg = g_rowptr[w], end = g_rowptr[w + 1];
    float di = g_dinv[w];
    const uint2* hb = (const uint2*)g_h1h;

    uint2 sv = hb[(size_t)w * 32 + lane];
    float2 s0 = __half22float2(*(__half2*)&sv.x);
    float2 s1 = __half22float2(*(__half2*)&sv.y);
    float s = di * di;
    float4 acc = make_float4(s0.x * s, s0.y * s, s1.x * s, s1.y * s);

    int p = beg;
    for (; p + 4 <= end; p += 4) {
        int2 e0 = g_edge[p], e1 = g_edge[p + 1], e2 = g_edge[p + 2], e3 = g_edge[p + 3];
        uint2 u0 = hb[(size_t)e0.x * 32 + lane];
        uint2 u1 = hb[(size_t)e1.x * 32 + lane];
        uint2 u2 = hb[(size_t)e2.x * 32 + lane];
        uint2 u3 = hb[(size_t)e3.x * 32 + lane];
        float w0 = __int_as_float(e0.y), w1 = __int_as_float(e1.y);
        float w2 = __int_as_float(e2.y), w3 = __int_as_float(e3.y);
        float2 a, b;
        a = __half22float2(*(__half2*)&u0.x); b = __half22float2(*(__half2*)&u0.y);
        acc.x += w0 * a.x; acc.y += w0 * a.y; acc.z += w0 * b.x; acc.w += w0 * b.y;
        a = __half22float2(*(__half2*)&u1.x); b = __half22float2(*(__half2*)&u1.y);
        acc.x += w1 * a.x; acc.y += w1 * a.y; acc.z += w1 * b.x; acc.w += w1 * b.y;
        a = __half22float2(*(__half2*)&u2.x); b = __half22float2(*(__half2*)&u2.y);
        acc.x += w2 * a.x; acc.y += w2 * a.y; acc.z += w2 * b.x; acc.w += w2 * b.y;
        a = __half22float2(*(__half2*)&u3.x); b = __half22float2(*(__half2*)&u3.y);
        acc.x += w3 * a.x; acc.y += w3 * a.y; acc.z += w3 * b.x; acc.w += w3 * b.y;
    }
    for (; p < end; p++) {
        int2 e0 = g_edge[p];
        uint2 u0 = hb[(size_t)e0.x * 32 + lane];
        float w0 = __int_as_float(e0.y);
        float2 a = __half22float2(*(__half2*)&u0.x);
        float2 b = __half22float2(*(__half2*)&u0.y);
        acc.x += w0 * a.x; acc.y += w0 * a.y; acc.z += w0 * b.x; acc.w += w0 * b.y;
    }
    ((float4*)g_agg1)[(size_t)w * 32 + lane] = acc;
}

// ---------------------------------------------------------------------------
// GEMM2: h2[n,64] = relu(agg1 + b1) @ W2[128,64], stored fp16
__global__ void k_gemm2(const float* __restrict__ b1, const float* __restrict__ W2, int n) {
    __shared__ float xs[64 * HID];
    __shared__ float bs[HID];
    int base = blockIdx.x * 64;
    if (threadIdx.x < HID) bs[threadIdx.x] = b1[threadIdx.x];
    __syncthreads();
    for (int i = threadIdx.x; i < 64 * HID; i += 256) {
        int node = i >> 7, k = i & 127;
        float v = (base + node < n) ? g_agg1[(size_t)(base + node) * HID + k] + bs[k] : 0.f;
        xs[i] = fmaxf(v, 0.f);
    }
    __syncthreads();
    int j4 = threadIdx.x & 15;   // 4 features
    int ng = threadIdx.x >> 4;   // 4 nodes
    const float4* Wv = (const float4*)W2;
    float acc[4][4];
#pragma unroll
    for (int t = 0; t < 4; t++) { acc[t][0]=acc[t][1]=acc[t][2]=acc[t][3]=0.f; }
#pragma unroll 4
    for (int k = 0; k < HID; k++) {
        float4 wk = Wv[k * 16 + j4];
#pragma unroll
        for (int t = 0; t < 4; t++) {
            float xx = xs[(ng * 4 + t) * HID + k];
            acc[t][0] += xx * wk.x;
            acc[t][1] += xx * wk.y;
            acc[t][2] += xx * wk.z;
            acc[t][3] += xx * wk.w;
        }
    }
    uint2* h2v = (uint2*)g_h2h;
#pragma unroll
    for (int t = 0; t < 4; t++) {
        int node = base + ng * 4 + t;
        if (node < n) {
            __half2 lo = __floats2half2_rn(acc[t][0], acc[t][1]);
            __half2 hi = __floats2half2_rn(acc[t][2], acc[t][3]);
            h2v[(size_t)node * 16 + j4] =
                make_uint2(*(unsigned*)&lo, *(unsigned*)&hi);
        }
    }
}

// ---------------------------------------------------------------------------
// Layer-2 pull aggregation + bias + ReLU: warp per node, 2 fp16 feats/lane.
__global__ void k_agg2(float* __restrict__ out, const float* __restrict__ b2, int n) {
    int w = (blockIdx.x * blockDim.x + threadIdx.x) >> 5;
    int lane = threadIdx.x & 31;
    if (w >= n) return;
    int beg = g_rowptr[w], end = g_rowptr[w + 1];
    float di = g_dinv[w];
    const unsigned* hb = (const unsigned*)g_h2h;

    unsigned sv = hb[(size_t)w * 32 + lane];
    float2 s0 = __half22float2(*(__half2*)&sv);
    float s = di * di;
    float2 acc = make_float2(s0.x * s, s0.y * s);

    int p = beg;
    for (; p + 4 <= end; p += 4) {
        int2 e0 = g_edge[p], e1 = g_edge[p + 1], e2 = g_edge[p + 2], e3 = g_edge[p + 3];
        unsigned u0 = hb[(size_t)e0.x * 32 + lane];
        unsigned u1 = hb[(size_t)e1.x * 32 + lane];
        unsigned u2 = hb[(size_t)e2.x * 32 + lane];
        unsigned u3 = hb[(size_t)e3.x * 32 + lane];
        float w0 = __int_as_float(e0.y), w1 = __int_as_float(e1.y);
        float w2 = __int_as_float(e2.y), w3 = __int_as_float(e3.y);
        float2 a;
        a = __half22float2(*(__half2*)&u0); acc.x += w0 * a.x; acc.y += w0 * a.y;
        a = __half22float2(*(__half2*)&u1); acc.x += w1 * a.x; acc.y += w1 * a.y;
        a = __half22float2(*(__half2*)&u2); acc.x += w2 * a.x; acc.y += w2 * a.y;
        a = __half22float2(*(__half2*)&u3); acc.x += w3 * a.x; acc.y += w3 * a.y;
    }
    for (; p < end; p++) {
        int2 e0 = g_edge[p];
        unsigned u0 = hb[(size_t)e0.x * 32 + lane];
        float w0 = __int_as_float(e0.y);
        float2 a = __half22float2(*(__half2*)&u0);
        acc.x += w0 * a.x; acc.y += w0 * a.y;
    }
    float bx = b2[lane * 2], by = b2[lane * 2 + 1];
    ((float2*)out)[(size_t)w * 32 + lane] =
        make_float2(fmaxf(acc.x + bx, 0.f), fmaxf(acc.y + by, 0.f));
}

// ---------------------------------------------------------------------------
extern "C" void kernel_launch(void* const* d_in, const int* in_sizes, int n_in,
                              void* d_out, int out_size) {
    const float* x  = (const float*)d_in[0];
    const int*   ei = (const int*)d_in[1];
    const float* W1 = (const float*)d_in[2];
    const float* b1 = (const float*)d_in[3];
    const float* W2 = (const float*)d_in[4];
    const float* b2 = (const float*)d_in[5];
    float* out = (float*)d_out;

    int n = in_sizes[0] / F_IN;
    int e = in_sizes[1] / 2;
    int nb = (n + 255) / 256;

    // one-time infra (created on first call = correctness run, outside capture;
    // identical launch sequence every call)
    static cudaStream_t s2 = nullptr;
    static cudaEvent_t evRoot = nullptr, evJoin = nullptr;
    if (!s2) {
        cudaStreamCreateWithFlags(&s2, cudaStreamNonBlocking);
        cudaEventCreateWithFlags(&evRoot, cudaEventDisableTiming);
        cudaEventCreateWithFlags(&evJoin, cudaEventDisableTiming);
    }

    void* cntPtr = nullptr;
    cudaGetSymbolAddress(&cntPtr, g_cnt);

    // fork: GEMM1 (x,W1 only) runs concurrently with the CSR build
    cudaEventRecord(evRoot, 0);
    cudaStreamWaitEvent(s2, evRoot, 0);
    k_gemm1<<<(n + 63) / 64, 256, 0, s2>>>(x, W1, n);
    cudaEventRecord(evJoin, s2);

    // CSR build chain on capture (default) stream
    cudaMemsetAsync(cntPtr, 0, (size_t)n * sizeof(int), 0);
    k_hist<<<(e + 255) / 256, 256>>>(ei, e);
    k_scan_a<<<nb, 256>>>(n);
    k_scan_c<<<nb, 256>>>(n, e);
    k_scatter<<<(e + 255) / 256, 256>>>(ei, e);

    // join: agg1 needs both h1 (s2) and CSR (default)
    cudaStreamWaitEvent(0, evJoin, 0);
    {
        long long thr = (long long)n * 32;
        k_agg1<<<(int)((thr + 255) / 256), 256>>>(n);
    }
    k_gemm2<<<(n + 63) / 64, 256>>>(b1, W2, n);
    {
        long long thr = (long long)n * 32;
        k_agg2<<<(int)((thr + 255) / 256), 256>>>(out, b2, n);
    }
}

// round 12
// speedup vs baseline: 1.5239x; 1.5145x over previous
#include <cuda_runtime.h>
#include <cuda_fp16.h>
#include <cstdint>

#define MAXN 50000
#define MAXE 1600000
#define F_IN 128
#define HID  128
#define F_OUT 64

// ---- scratch (device globals; no allocation allowed) ----
__device__ int    g_cnt[MAXN];
__device__ int    g_rowtmp[MAXN];
__device__ int    g_bsum[256];
__device__ int    g_rowptr[MAXN + 1];
__device__ int    g_wp[MAXN];
__device__ float  g_dinv[MAXN];
__device__ int2   g_edge[MAXE];                 // .x = src, .y = bits(norm)
__device__ __half g_h1h[(size_t)MAXN * HID];    // fp16 x@W1 (gather operand)
__device__ float  g_agg1[(size_t)MAXN * HID];   // fp32 aggregated layer-1
__device__ __half g_h2h[(size_t)MAXN * F_OUT];  // fp16 layer-2 pre-agg

// ---- mma helpers -----------------------------------------------------------
static __device__ __forceinline__ uint32_t saddr(const void* p) {
    return (uint32_t)__cvta_generic_to_shared(p);
}
#define LDSM_X4(r0, r1, r2, r3, a) \
    asm volatile("ldmatrix.sync.aligned.m8n8.x4.shared.b16 {%0,%1,%2,%3},[%4];" \
                 : "=r"(r0), "=r"(r1), "=r"(r2), "=r"(r3) : "r"(a))
#define LDSM_X4_T(r0, r1, r2, r3, a) \
    asm volatile("ldmatrix.sync.aligned.m8n8.x4.trans.shared.b16 {%0,%1,%2,%3},[%4];" \
                 : "=r"(r0), "=r"(r1), "=r"(r2), "=r"(r3) : "r"(a))
#define MMA16816(C, A, B0, B1) \
    asm volatile("mma.sync.aligned.m16n8k16.row.col.f32.f16.f16.f32 " \
                 "{%0,%1,%2,%3},{%4,%5,%6,%7},{%8,%9},{%0,%1,%2,%3};" \
                 : "+f"((C)[0]), "+f"((C)[1]), "+f"((C)[2]), "+f"((C)[3]) \
                 : "r"((A)[0]), "r"((A)[1]), "r"((A)[2]), "r"((A)[3]), \
                   "r"(B0), "r"(B1))

#define LDA 136  // padded smem row stride in halves (272B: conflict-free ldmatrix)
#define LDB2 72  // W2 smem stride in halves (144B)

// ---------------------------------------------------------------------------
__global__ void k_hist(const int* __restrict__ ei, int e) {
    int i = blockIdx.x * blockDim.x + threadIdx.x;
    if (i < e) atomicAdd(&g_cnt[ei[e + i]], 1);
}

__global__ void k_scan_a(int n) {
    __shared__ int s[256];
    int i = blockIdx.x * 256 + threadIdx.x;
    int v = (i < n) ? g_cnt[i] : 0;
    s[threadIdx.x] = v;
    __syncthreads();
#pragma unroll
    for (int off = 1; off < 256; off <<= 1) {
        int t = (threadIdx.x >= off) ? s[threadIdx.x - off] : 0;
        __syncthreads();
        s[threadIdx.x] += t;
        __syncthreads();
    }
    if (i < n) g_rowtmp[i] = s[threadIdx.x];
    if (threadIdx.x == 255) g_bsum[blockIdx.x] = s[255];
}

__global__ void k_scan_c(int n, int e) {
    __shared__ int red[8];
    __shared__ int s_off;
    int partial = 0;
    for (int j = threadIdx.x; j < blockIdx.x; j += 256) partial += g_bsum[j];
#pragma unroll
    for (int o = 16; o; o >>= 1) partial += __shfl_down_sync(0xffffffffu, partial, o);
    if ((threadIdx.x & 31) == 0) red[threadIdx.x >> 5] = partial;
    __syncthreads();
    if (threadIdx.x == 0) {
        int t = 0;
#pragma unroll
        for (int k = 0; k < 8; k++) t += red[k];
        s_off = t;
    }
    __syncthreads();
    int i = blockIdx.x * 256 + threadIdx.x;
    if (i < n) {
        int c = g_cnt[i];
        int rp = s_off + g_rowtmp[i] - c;
        g_rowptr[i] = rp;
        g_wp[i] = rp;
        g_dinv[i] = rsqrtf((float)c + 1.0f);
    }
    if (i == 0) g_rowptr[n] = e;
}

__global__ void k_scatter(const int* __restrict__ ei, int e) {
    int i = blockIdx.x * blockDim.x + threadIdx.x;
    if (i >= e) return;
    int src = ei[i], dst = ei[e + i];
    int pos = atomicAdd(&g_wp[dst], 1);
    float nrm = g_dinv[src] * g_dinv[dst];
    g_edge[pos] = make_int2(src, __float_as_int(nrm));
}

// ---------------------------------------------------------------------------
// GEMM1 (tensor core): h1h[n,128] = fp16(x[n,128] @ W1[128,128]), fp32 acc.
// 256 thr / 8 warps; tile = 128 rows x 128 cols x full K=128.
__global__ __launch_bounds__(256) void k_gemm1_tc(
    const float* __restrict__ x, const float* __restrict__ W1, int n) {
    extern __shared__ __half sm1[];
    __half* sx = sm1;               // [128][LDA]
    __half* sw = sm1 + 128 * LDA;   // [128][LDA]
    int tid = threadIdx.x;
    int base = blockIdx.x * 128;

    for (int i = tid; i < 128 * 32; i += 256) {   // 32 float4 per row
        int r = i >> 5, c4 = i & 31;
        float4 v = (base + r < n) ? ((const float4*)x)[(size_t)(base + r) * 32 + c4]
                                  : make_float4(0.f, 0.f, 0.f, 0.f);
        *(__half2*)&sx[r * LDA + c4 * 4]     = __floats2half2_rn(v.x, v.y);
        *(__half2*)&sx[r * LDA + c4 * 4 + 2] = __floats2half2_rn(v.z, v.w);
    }
    for (int i = tid; i < 128 * 32; i += 256) {
        int r = i >> 5, c4 = i & 31;
        float4 v = ((const float4*)W1)[r * 32 + c4];
        *(__half2*)&sw[r * LDA + c4 * 4]     = __floats2half2_rn(v.x, v.y);
        *(__half2*)&sw[r * LDA + c4 * 4 + 2] = __floats2half2_rn(v.z, v.w);
    }
    __syncthreads();

    int warp = tid >> 5, lane = tid & 31;
    int m0 = warp * 16;
    int lr = (lane & 7) + ((lane >> 3) & 1) * 8;  // ldmatrix row within 16
    int lc = (lane >> 4) * 8;                     // ldmatrix col within 16

    float acc[16][4];
#pragma unroll
    for (int t = 0; t < 16; t++) { acc[t][0]=acc[t][1]=acc[t][2]=acc[t][3]=0.f; }

#pragma unroll
    for (int k0 = 0; k0 < 128; k0 += 16) {
        uint32_t a0, a1, a2, a3;
        LDSM_X4(a0, a1, a2, a3, saddr(&sx[(m0 + lr) * LDA + k0 + lc]));
        uint32_t A[4] = {a0, a1, a2, a3};
#pragma unroll
        for (int t2 = 0; t2 < 8; t2++) {           // 16-col chunks of N
            uint32_t b0, b1, b2, b3;
            LDSM_X4_T(b0, b1, b2, b3, saddr(&sw[(k0 + lr) * LDA + t2 * 16 + lc]));
            MMA16816(acc[2 * t2],     A, b0, b1);
            MMA16816(acc[2 * t2 + 1], A, b2, b3);
        }
    }
    int r_lo = base + m0 + (lane >> 2);
    int r_hi = r_lo + 8;
#pragma unroll
    for (int t = 0; t < 16; t++) {
        int col = t * 8 + (lane & 3) * 2;
        if (r_lo < n)
            *(__half2*)&g_h1h[(size_t)r_lo * HID + col] = __floats2half2_rn(acc[t][0], acc[t][1]);
        if (r_hi < n)
            *(__half2*)&g_h1h[(size_t)r_hi * HID + col] = __floats2half2_rn(acc[t][2], acc[t][3]);
    }
}

// ---------------------------------------------------------------------------
// GEMM2 (tensor core): h2h[n,64] = fp16( relu(agg1+b1)[n,128] @ W2[128,64] )
__global__ __launch_bounds__(256) void k_gemm2_tc(
    const float* __restrict__ b1, const float* __restrict__ W2, int n) {
    extern __shared__ __half sm2[];
    __half* sx = sm2;               // [128][LDA]
    __half* sw = sm2 + 128 * LDA;   // [128][LDB2]
    __shared__ float bs[HID];
    int tid = threadIdx.x;
    int base = blockIdx.x * 128;

    if (tid < HID) bs[tid] = b1[tid];
    __syncthreads();

    for (int i = tid; i < 128 * 32; i += 256) {
        int r = i >> 5, c4 = i & 31;
        float4 v = (base + r < n) ? ((const float4*)g_agg1)[(size_t)(base + r) * 32 + c4]
                                  : make_float4(0.f, 0.f, 0.f, 0.f);
        int c = c4 * 4;
        v.x = fmaxf(v.x + bs[c], 0.f);
        v.y = fmaxf(v.y + bs[c + 1], 0.f);
        v.z = fmaxf(v.z + bs[c + 2], 0.f);
        v.w = fmaxf(v.w + bs[c + 3], 0.f);
        *(__half2*)&sx[r * LDA + c]     = __floats2half2_rn(v.x, v.y);
        *(__half2*)&sx[r * LDA + c + 2] = __floats2half2_rn(v.z, v.w);
    }
    for (int i = tid; i < 128 * 16; i += 256) {   // W2: 128x64 = 128x16 float4
        int r = i >> 4, c4 = i & 15;
        float4 v = ((const float4*)W2)[r * 16 + c4];
        *(__half2*)&sw[r * LDB2 + c4 * 4]     = __floats2half2_rn(v.x, v.y);
        *(__half2*)&sw[r * LDB2 + c4 * 4 + 2] = __floats2half2_rn(v.z, v.w);
    }
    __syncthreads();

    int warp = tid >> 5, lane = tid & 31;
    int m0 = warp * 16;
    int lr = (lane & 7) + ((lane >> 3) & 1) * 8;
    int lc = (lane >> 4) * 8;

    float acc[8][4];
#pragma unroll
    for (int t = 0; t < 8; t++) { acc[t][0]=acc[t][1]=acc[t][2]=acc[t][3]=0.f; }

#pragma unroll
    for (int k0 = 0; k0 < 128; k0 += 16) {
        uint32_t a0, a1, a2, a3;
        LDSM_X4(a0, a1, a2, a3, saddr(&sx[(m0 + lr) * LDA + k0 + lc]));
        uint32_t A[4] = {a0, a1, a2, a3};
#pragma unroll
        for (int t2 = 0; t2 < 4; t2++) {           // 16-col chunks of N=64
            uint32_t b0, b1v, b2, b3;
            LDSM_X4_T(b0, b1v, b2, b3, saddr(&sw[(k0 + lr) * LDB2 + t2 * 16 + lc]));
            MMA16816(acc[2 * t2],     A, b0, b1v);
            MMA16816(acc[2 * t2 + 1], A, b2, b3);
        }
    }
    int r_lo = base + m0 + (lane >> 2);
    int r_hi = r_lo + 8;
#pragma unroll
    for (int t = 0; t < 8; t++) {
        int col = t * 8 + (lane & 3) * 2;
        if (r_lo < n)
            *(__half2*)&g_h2h[(size_t)r_lo * F_OUT + col] = __floats2half2_rn(acc[t][0], acc[t][1]);
        if (r_hi < n)
            *(__half2*)&g_h2h[(size_t)r_hi * F_OUT + col] = __floats2half2_rn(acc[t][2], acc[t][3]);
    }
}

// ---------------------------------------------------------------------------
// Layer-1 pull aggregation: warp per node, 4 fp16 feats/lane, fp32 acc.
__global__ void k_agg1(int n) {
    int w = (blockIdx.x * blockDim.x + threadIdx.x) >> 5;
    int lane = threadIdx.x & 31;
    if (w >= n) return;
    int beg = g_rowptr[w], end = g_rowptr[w + 1];
    float di = g_dinv[w];
    const uint2* hb = (const uint2*)g_h1h;

    uint2 sv = hb[(size_t)w * 32 + lane];
    float2 s0 = __half22float2(*(__half2*)&sv.x);
    float2 s1 = __half22float2(*(__half2*)&sv.y);
    float s = di * di;
    float4 acc = make_float4(s0.x * s, s0.y * s, s1.x * s, s1.y * s);

    int p = beg;
    for (; p + 4 <= end; p += 4) {
        int2 e0 = g_edge[p], e1 = g_edge[p + 1], e2 = g_edge[p + 2], e3 = g_edge[p + 3];
        uint2 u0 = hb[(size_t)e0.x * 32 + lane];
        uint2 u1 = hb[(size_t)e1.x * 32 + lane];
        uint2 u2 = hb[(size_t)e2.x * 32 + lane];
        uint2 u3 = hb[(size_t)e3.x * 32 + lane];
        float w0 = __int_as_float(e0.y), w1 = __int_as_float(e1.y);
        float w2 = __int_as_float(e2.y), w3 = __int_as_float(e3.y);
        float2 a, b;
        a = __half22float2(*(__half2*)&u0.x); b = __half22float2(*(__half2*)&u0.y);
        acc.x += w0 * a.x; acc.y += w0 * a.y; acc.z += w0 * b.x; acc.w += w0 * b.y;
        a = __half22float2(*(__half2*)&u1.x); b = __half22float2(*(__half2*)&u1.y);
        acc.x += w1 * a.x; acc.y += w1 * a.y; acc.z += w1 * b.x; acc.w += w1 * b.y;
        a = __half22float2(*(__half2*)&u2.x); b = __half22float2(*(__half2*)&u2.y);
        acc.x += w2 * a.x; acc.y += w2 * a.y; acc.z += w2 * b.x; acc.w += w2 * b.y;
        a = __half22float2(*(__half2*)&u3.x); b = __half22float2(*(__half2*)&u3.y);
        acc.x += w3 * a.x; acc.y += w3 * a.y; acc.z += w3 * b.x; acc.w += w3 * b.y;
    }
    for (; p < end; p++) {
        int2 e0 = g_edge[p];
        uint2 u0 = hb[(size_t)e0.x * 32 + lane];
        float w0 = __int_as_float(e0.y);
        float2 a = __half22float2(*(__half2*)&u0.x);
        float2 b = __half22float2(*(__half2*)&u0.y);
        acc.x += w0 * a.x; acc.y += w0 * a.y; acc.z += w0 * b.x; acc.w += w0 * b.y;
    }
    ((float4*)g_agg1)[(size_t)w * 32 + lane] = acc;
}

// ---------------------------------------------------------------------------
// Layer-2 pull aggregation + bias + ReLU: warp per node, 2 fp16 feats/lane.
__global__ void k_agg2(float* __restrict__ out, const float* __restrict__ b2, int n) {
    int w = (blockIdx.x * blockDim.x + threadIdx.x) >> 5;
    int lane = threadIdx.x & 31;
    if (w >= n) return;
    int beg = g_rowptr[w], end = g_rowptr[w + 1];
    float di = g_dinv[w];
    const unsigned* hb = (const unsigned*)g_h2h;

    unsigned sv = hb[(size_t)w * 32 + lane];
    float2 s0 = __half22float2(*(__half2*)&sv);
    float s = di * di;
    float2 acc = make_float2(s0.x * s, s0.y * s);

    int p = beg;
    for (; p + 4 <= end; p += 4) {
        int2 e0 = g_edge[p], e1 = g_edge[p + 1], e2 = g_edge[p + 2], e3 = g_edge[p + 3];
        unsigned u0 = hb[(size_t)e0.x * 32 + lane];
        unsigned u1 = hb[(size_t)e1.x * 32 + lane];
        unsigned u2 = hb[(size_t)e2.x * 32 + lane];
        unsigned u3 = hb[(size_t)e3.x * 32 + lane];
        float w0 = __int_as_float(e0.y), w1 = __int_as_float(e1.y);
        float w2 = __int_as_float(e2.y), w3 = __int_as_float(e3.y);
        float2 a;
        a = __half22float2(*(__half2*)&u0); acc.x += w0 * a.x; acc.y += w0 * a.y;
        a = __half22float2(*(__half2*)&u1); acc.x += w1 * a.x; acc.y += w1 * a.y;
        a = __half22float2(*(__half2*)&u2); acc.x += w2 * a.x; acc.y += w2 * a.y;
        a = __half22float2(*(__half2*)&u3); acc.x += w3 * a.x; acc.y += w3 * a.y;
    }
    for (; p < end; p++) {
        int2 e0 = g_edge[p];
        unsigned u0 = hb[(size_t)e0.x * 32 + lane];
        float w0 = __int_as_float(e0.y);
        float2 a = __half22float2(*(__half2*)&u0);
        acc.x += w0 * a.x; acc.y += w0 * a.y;
    }
    float bx = b2[lane * 2], by = b2[lane * 2 + 1];
    ((float2*)out)[(size_t)w * 32 + lane] =
        make_float2(fmaxf(acc.x + bx, 0.f), fmaxf(acc.y + by, 0.f));
}

// ---------------------------------------------------------------------------
extern "C" void kernel_launch(void* const* d_in, const int* in_sizes, int n_in,
                              void* d_out, int out_size) {
    const float* x  = (const float*)d_in[0];
    const int*   ei = (const int*)d_in[1];
    const float* W1 = (const float*)d_in[2];
    const float* b1 = (const float*)d_in[3];
    const float* W2 = (const float*)d_in[4];
    const float* b2 = (const float*)d_in[5];
    float* out = (float*)d_out;

    int n = in_sizes[0] / F_IN;
    int e = in_sizes[1] / 2;
    int nb = (n + 255) / 256;

    const int SMEM1 = 2 * 128 * LDA * (int)sizeof(__half);           // 69632
    const int SMEM2 = (128 * LDA + 128 * LDB2) * (int)sizeof(__half); // 53248

    static cudaStream_t s2 = nullptr;
    static cudaEvent_t evRoot = nullptr, evJoin = nullptr;
    if (!s2) {
        cudaStreamCreateWithFlags(&s2, cudaStreamNonBlocking);
        cudaEventCreateWithFlags(&evRoot, cudaEventDisableTiming);
        cudaEventCreateWithFlags(&evJoin, cudaEventDisableTiming);
        cudaFuncSetAttribute(k_gemm1_tc, cudaFuncAttributeMaxDynamicSharedMemorySize, SMEM1);
        cudaFuncSetAttribute(k_gemm2_tc, cudaFuncAttributeMaxDynamicSharedMemorySize, SMEM2);
    }

    void* cntPtr = nullptr;
    cudaGetSymbolAddress(&cntPtr, g_cnt);

    // fork: GEMM1 (x,W1 only) runs concurrently with the CSR build
    cudaEventRecord(evRoot, 0);
    cudaStreamWaitEvent(s2, evRoot, 0);
    k_gemm1_tc<<<(n + 127) / 128, 256, SMEM1, s2>>>(x, W1, n);
    cudaEventRecord(evJoin, s2);

    // CSR build chain on capture (default) stream
    cudaMemsetAsync(cntPtr, 0, (size_t)n * sizeof(int), 0);
    k_hist<<<(e + 255) / 256, 256>>>(ei, e);
    k_scan_a<<<nb, 256>>>(n);
    k_scan_c<<<nb, 256>>>(n, e);
    k_scatter<<<(e + 255) / 256, 256>>>(ei, e);

    // join: agg1 needs both h1 (s2) and CSR (default)
    cudaStreamWaitEvent(0, evJoin, 0);
    {
        long long thr = (long long)n * 32;
        k_agg1<<<(int)((thr + 255) / 256), 256>>>(n);
    }
    k_gemm2_tc<<<(n + 127) / 128, 256, SMEM2>>>(b1, W2, n);
    {
        long long thr = (long long)n * 32;
        k_agg2<<<(int)((thr + 255) / 256), 256>>>(out, b2, n);
    }
}